// round 3
// baseline (speedup 1.0000x reference)
#include <cuda_runtime.h>

// ============================================================================
// QPIE circuit simulator, branch-path-per-warp, fully register-resident.
//
// Physics reduction:
//  - 8 data qubits only; ancilla block (H, diagonal CRZ, [H], SWAP->record)
//    collapses to a per-branch multiplicative factor G0(r0,d)*G1(r1,d).
//  - Records appear only as CCRX controls with known per-branch values.
//  - 64 branch paths per batch; each warp simulates one full path on a
//    256-amplitude state (8 complex amps per lane, qubits 0-4 = lane bits,
//    qubits 5-7 = register index). Final evs = sum over paths (atomicAdd).
// ============================================================================

struct Cplx { float re, im; };
__device__ __forceinline__ Cplx cmul(Cplx a, Cplx b) {
    return { a.re*b.re - a.im*b.im, a.re*b.im + a.im*b.re };
}

// Single-qubit gate U on qubit Q. new|0> = u00 v0 + u01 v1 ; new|1> = u10 v0 + u11 v1
template<int Q>
__device__ __forceinline__ void apply1(float (&re)[8], float (&im)[8], unsigned lane,
                                       Cplx u00, Cplx u01, Cplx u10, Cplx u11) {
    if constexpr (Q < 5) {
        constexpr int m = 1 << Q;
        const bool hi = (lane & m) != 0;
#pragma unroll
        for (int r = 0; r < 8; r++) {
            float ore = __shfl_xor_sync(0xffffffffu, re[r], m);
            float oim = __shfl_xor_sync(0xffffffffu, im[r], m);
            float vre = re[r], vim = im[r];
            Cplx a = hi ? u11 : u00;  // coeff of own amplitude
            Cplx b = hi ? u10 : u01;  // coeff of partner amplitude
            re[r] = a.re*vre - a.im*vim + b.re*ore - b.im*oim;
            im[r] = a.re*vim + a.im*vre + b.re*oim + b.im*ore;
        }
    } else {
        constexpr int rb = 1 << (Q - 5);
#pragma unroll
        for (int r = 0; r < 8; r++) {
            if (r & rb) continue;
            constexpr int dummy = 0; (void)dummy;
            const int r1 = r | rb;
            float v0r = re[r],  v0i = im[r];
            float v1r = re[r1], v1i = im[r1];
            re[r]  = u00.re*v0r - u00.im*v0i + u01.re*v1r - u01.im*v1i;
            im[r]  = u00.re*v0i + u00.im*v0r + u01.re*v1i + u01.im*v1r;
            re[r1] = u10.re*v0r - u10.im*v0i + u11.re*v1r - u11.im*v1i;
            im[r1] = u10.re*v0i + u10.im*v0r + u11.re*v1i + u11.im*v1r;
        }
    }
}

// Fused RXX(tx)*RYY(ty)*RZZ(tz) on (Q1,Q2). Acts in 2D subspaces {same parity},
// {diff parity}: new = phase * (cos(.)v - i sin(.) v_flipboth)
//   same parity: angle (tx-ty)/2, phase e^{-i tz/2}
//   diff parity: angle (tx+ty)/2, phase e^{+i tz/2}
template<int Q1, int Q2>
__device__ __forceinline__ void xxyyzz(float (&re)[8], float (&im)[8], unsigned lane,
                                       float tx, float ty, float tz) {
    float sd, cd, ss, cs, sz, cz;
    __sincosf(0.5f*(tx - ty), &sd, &cd);
    __sincosf(0.5f*(tx + ty), &ss, &cs);
    __sincosf(0.5f*tz,        &sz, &cz);
    constexpr int lm = ((Q1 < 5) ? (1 << Q1) : 0) | ((Q2 < 5) ? (1 << Q2) : 0);
    constexpr int rm = ((Q1 >= 5) ? (1 << (Q1-5)) : 0) | ((Q2 >= 5) ? (1 << (Q2-5)) : 0);
    float nre[8], nim[8];
#pragma unroll
    for (int r = 0; r < 8; r++) {
        const int pr = r ^ rm;
        float wre = re[pr], wim = im[pr];
        if constexpr (lm != 0) {
            wre = __shfl_xor_sync(0xffffffffu, wre, lm);
            wim = __shfl_xor_sync(0xffffffffu, wim, lm);
        }
        const int d = (r << 5) | (int)lane;
        const int p = ((d >> Q1) ^ (d >> Q2)) & 1;
        float c    = p ? cs : cd;
        float s    = p ? ss : sd;
        float phre = cz;
        float phim = p ? sz : -sz;
        // t = c*v - i*s*w
        float tre = c*re[r] + s*wim;
        float tim = c*im[r] - s*wre;
        nre[r] = phre*tre - phim*tim;
        nim[r] = phre*tim + phim*tre;
    }
#pragma unroll
    for (int r = 0; r < 8; r++) { re[r] = nre[r]; im[r] = nim[r]; }
}

// Controlled-RX(pi/4): control QC, target QT (both lane qubits in our usage).
template<int QC, int QT>
__device__ __forceinline__ void crx8(float (&re)[8], float (&im)[8], unsigned lane) {
    const float c = 0.92387953251128674f;   // cos(pi/8)
    const float s = 0.38268343236508977f;   // sin(pi/8)
    constexpr int m = 1 << QT;
    const bool ctrl = ((lane >> QC) & 1) != 0;
#pragma unroll
    for (int r = 0; r < 8; r++) {
        float wre = __shfl_xor_sync(0xffffffffu, re[r], m);
        float wim = __shfl_xor_sync(0xffffffffu, im[r], m);
        if (ctrl) {
            float nr = c*re[r] + s*wim;   // c*v - i*s*w
            float ni = c*im[r] - s*wre;
            re[r] = nr; im[r] = ni;
        }
    }
}

// Branch factor for one ancilla: even layer G(r) = e^{-(-1)^r i s/2}/sqrt(2);
// odd layer (extra H): G(0)=cos(s/2), G(1)=-i sin(s/2).
__device__ __forceinline__ Cplx splitG(bool even, int rv, float s) {
    float sn, csn;
    __sincosf(0.5f*s, &sn, &csn);
    if (even) {
        const float k = 0.70710678118654752f;
        return { k*csn, rv ? k*sn : -k*sn };
    } else {
        return rv ? Cplx{0.f, -sn} : Cplx{csn, 0.f};
    }
}

#define ROT1(Q) { float c_, s_; __sincosf(0.5f*xb[Q], &s_, &c_);                       \
    if (even) apply1<Q>(re, im, lane, Cplx{c_,0.f}, Cplx{-s_,0.f},                     \
                        Cplx{s_,0.f}, Cplx{c_,0.f});                                   \
    else      apply1<Q>(re, im, lane, Cplx{c_,0.f}, Cplx{0.f,-s_},                     \
                        Cplx{0.f,-s_}, Cplx{c_,0.f}); }

// Fused RZ(tz)*RY(ty)*RX(tx) (RX applied first, as in reference).
#define VROT(Q) {                                                                      \
    float cx_, sx_, cy_, sy_, cz_, sz_;                                                \
    __sincosf(0.5f*wl[24 + 3*Q], &sx_, &cx_);                                          \
    __sincosf(0.5f*wl[25 + 3*Q], &sy_, &cy_);                                          \
    __sincosf(0.5f*wl[26 + 3*Q], &sz_, &cz_);                                          \
    Cplx a00{cx_*cy_,  sx_*sy_}, a01{-sy_*cx_, -sx_*cy_};                              \
    Cplx a10{ sy_*cx_, -sx_*cy_}, a11{ cx_*cy_, -sx_*sy_};                             \
    Cplx e0{cz_, -sz_}, e1{cz_, sz_};                                                  \
    apply1<Q>(re, im, lane, cmul(e0,a00), cmul(e0,a01), cmul(e1,a10), cmul(e1,a11)); }

__global__ void __launch_bounds__(128)
qpie_kernel(const float* __restrict__ x, const float* __restrict__ w,
            const float* __restrict__ pw, float* __restrict__ out) {
    const unsigned lane  = threadIdx.x & 31u;
    const int warpId     = threadIdx.x >> 5;
    const int batch      = blockIdx.x >> 4;                  // 16 blocks per batch
    const int path       = ((blockIdx.x & 15) << 2) | warpId; // 0..63
    const float* xb = x + batch * 8;

    float re[8], im[8];
#pragma unroll
    for (int r = 0; r < 8; r++) { re[r] = 1.f; im[r] = 0.f; }   // H^8|0..0>, scale 16 deferred

    for (int layer = 0; layer < 3; layer++) {
        const float* wl  = w  + layer * 48;
        const float* pwl = pw + layer * 16;
        const int r0 = (path >> (2*layer))     & 1;
        const int r1 = (path >> (2*layer + 1)) & 1;
        const bool even = (layer & 1) == 0;

        // 1. data rotations rot(x[q]): RY even layers, RX odd layers
        ROT1(0) ROT1(1) ROT1(2) ROT1(3) ROT1(4) ROT1(5) ROT1(6) ROT1(7)

        // 2. ancilla block -> per-branch scalar factor G0(r0,d)*G1(r1,d)
        {
            float sl0 = 0.f, sl1 = 0.f;
#pragma unroll
            for (int j = 0; j < 5; j++) {
                float b = (float)((lane >> j) & 1);
                sl0 += b * pwl[j];
                sl1 += b * pwl[8 + j];
            }
#pragma unroll
            for (int r = 0; r < 8; r++) {
                float s0 = sl0, s1 = sl1;
                if (r & 1) { s0 += pwl[5]; s1 += pwl[13]; }
                if (r & 2) { s0 += pwl[6]; s1 += pwl[14]; }
                if (r & 4) { s0 += pwl[7]; s1 += pwl[15]; }
                Cplx g = cmul(splitG(even, r0, s0), splitG(even, r1, s1));
                float vr = re[r], vi = im[r];
                re[r] = g.re*vr - g.im*vi;
                im[r] = g.re*vi + g.im*vr;
            }
        }

        // 3. entanglers: pairs + CCRX (record control folded into branch), off-pairs
        xxyyzz<0,1>(re, im, lane, wl[0],  wl[1],  wl[2]);
        if (r0) crx8<0,1>(re, im, lane);
        xxyyzz<2,3>(re, im, lane, wl[3],  wl[4],  wl[5]);
        if (r1) crx8<2,3>(re, im, lane);
        xxyyzz<4,5>(re, im, lane, wl[6],  wl[7],  wl[8]);
        xxyyzz<6,7>(re, im, lane, wl[9],  wl[10], wl[11]);
        xxyyzz<1,2>(re, im, lane, wl[12], wl[13], wl[14]);
        xxyyzz<3,4>(re, im, lane, wl[15], wl[16], wl[17]);
        xxyyzz<5,6>(re, im, lane, wl[18], wl[19], wl[20]);

        // 4. per-qubit RX*RY*RZ (fused 2x2)
        VROT(0) VROT(1) VROT(2) VROT(3) VROT(4) VROT(5) VROT(6) VROT(7)
    }

    // Measurement: ev[q] = sum_d |amp|^2 * (1 - 2*d_q), scaled by 1/256 (initial 1/16 amp)
    float ev[8];
#pragma unroll
    for (int q = 0; q < 8; q++) ev[q] = 0.f;
#pragma unroll
    for (int r = 0; r < 8; r++) {
        float p = re[r]*re[r] + im[r]*im[r];
        const int d = (r << 5) | (int)lane;
#pragma unroll
        for (int q = 0; q < 8; q++)
            ev[q] += ((d >> q) & 1) ? -p : p;
    }
#pragma unroll
    for (int off = 16; off >= 1; off >>= 1) {
#pragma unroll
        for (int q = 0; q < 8; q++)
            ev[q] += __shfl_xor_sync(0xffffffffu, ev[q], off);
    }

    __shared__ float sOut[8];
    if (threadIdx.x < 8) sOut[threadIdx.x] = 0.f;
    __syncthreads();
    if (lane < 8) atomicAdd(&sOut[lane], ev[lane]);
    __syncthreads();
    if (threadIdx.x < 8)
        atomicAdd(&out[batch*8 + threadIdx.x], sOut[threadIdx.x] * (1.f/256.f));
}

__global__ void zero_kernel(float* out, int n) {
    int i = blockIdx.x * blockDim.x + threadIdx.x;
    if (i < n) out[i] = 0.f;
}

extern "C" void kernel_launch(void* const* d_in, const int* in_sizes, int n_in,
                              void* d_out, int out_size) {
    const float* x  = (const float*)d_in[0];   // [B, 8]
    const float* w  = (const float*)d_in[1];   // [3, 48]
    const float* pw = (const float*)d_in[2];   // [3, 2, 8]
    float* out = (float*)d_out;                // [B, 8]

    const int nb = in_sizes[0] / 8;            // batch count (16)
    zero_kernel<<<(out_size + 127) / 128, 128>>>(out, out_size);
    qpie_kernel<<<nb * 16, 128>>>(x, w, pw, out);
}

// round 4
// speedup vs baseline: 1.0155x; 1.0155x over previous
#include <cuda_runtime.h>

// ============================================================================
// QPIE simulator v3: branch-path-per-warp, register-resident, with all
// batch/path-invariant trig precomputed into device tables.
//
//  - Initial state = product state (H then RY(x) per qubit) -> free layer-1 ROT.
//  - Layer-boundary fusion: VROT(layer L) * ROT(x, layer L+1) = one 2x2.
//  - Branch factors g(layer, r0r1, d) tabulated (24 KB, L2-resident).
//  - Entangler coefficient triples tabulated.
//  - Launch: 128 blocks x 256 threads = 1 block/SM, one balanced wave.
// ============================================================================

struct Cplx { float re, im; };
__device__ __forceinline__ Cplx cmul(Cplx a, Cplx b) {
    return { a.re*b.re - a.im*b.im, a.re*b.im + a.im*b.re };
}

// ---------------- device tables ----------------
__device__ float2 g_branch[3 * 4 * 256];     // [layer][r0+2*r1][d]
__device__ float4 g_bmat[16 * 2 * 8 * 2];    // [batch][bnd][q][row]; row0=(u00,u01) row1=(u10,u11)
__device__ float4 g_vrot[8 * 2];             // final-layer VROT [q][row]
__device__ float  g_xyz[3 * 7 * 6];          // [layer][pair]: cd,sd,cs,ss,cz,sz
__device__ float2 g_init[16 * 8];            // [batch][q] = (a0,a1) real init factors

// ---------------- precompute helpers ----------------
struct C2 { Cplx m[2][2]; };
__device__ __forceinline__ C2 c2mul(C2 A, C2 B) {
    C2 R;
    for (int i = 0; i < 2; i++)
        for (int j = 0; j < 2; j++) {
            Cplx s{0.f, 0.f};
            for (int k = 0; k < 2; k++) {
                Cplx p = cmul(A.m[i][k], B.m[k][j]);
                s.re += p.re; s.im += p.im;
            }
            R.m[i][j] = s;
        }
    return R;
}
__device__ __forceinline__ C2 mRX(float t) {
    float s, c; sincosf(0.5f*t, &s, &c);
    return C2{{{{c,0.f},{0.f,-s}},{{0.f,-s},{c,0.f}}}};
}
__device__ __forceinline__ C2 mRY(float t) {
    float s, c; sincosf(0.5f*t, &s, &c);
    return C2{{{{c,0.f},{-s,0.f}},{{s,0.f},{c,0.f}}}};
}
__device__ __forceinline__ C2 mRZ(float t) {
    float s, c; sincosf(0.5f*t, &s, &c);
    return C2{{{{c,-s},{0.f,0.f}},{{0.f,0.f},{c,s}}}};
}
__device__ __forceinline__ Cplx splitG(bool even, int rv, float s) {
    float sn, cn; sincosf(0.5f*s, &sn, &cn);
    if (even) {
        const float k = 0.70710678118654752f;
        return { k*cn, rv ? k*sn : -k*sn };
    }
    return rv ? Cplx{0.f, -sn} : Cplx{cn, 0.f};
}

__global__ void qpie_precompute(const float* __restrict__ x,
                                const float* __restrict__ w,
                                const float* __restrict__ pw,
                                float* __restrict__ out, int out_n, int nb) {
    int t = blockIdx.x * blockDim.x + threadIdx.x;

    if (t < 3072) {                                  // branch factor table
        int layer = t >> 10, rem = t & 1023;
        int combo = rem >> 8, d = rem & 255;
        int r0 = combo & 1, r1 = combo >> 1;
        bool even = (layer & 1) == 0;
        float s0 = 0.f, s1 = 0.f;
        for (int j = 0; j < 8; j++) {
            float b = (float)((d >> j) & 1);
            s0 += b * pw[layer*16 + j];
            s1 += b * pw[layer*16 + 8 + j];
        }
        Cplx g = cmul(splitG(even, r0, s0), splitG(even, r1, s1));
        g_branch[t] = make_float2(g.re, g.im);
        return;
    }
    t -= 3072;
    if (t < 256) {                                   // fused boundary matrices
        int batch = t >> 4, rem = t & 15;
        int bnd = rem >> 3, q = rem & 7;
        if (batch < nb) {
            const float* wl = w + bnd * 48;
            C2 V = c2mul(mRZ(wl[26 + 3*q]), c2mul(mRY(wl[25 + 3*q]), mRX(wl[24 + 3*q])));
            C2 R = (bnd == 0) ? mRX(x[batch*8 + q]) : mRY(x[batch*8 + q]);
            C2 M = c2mul(R, V);
            int base = ((batch*2 + bnd)*8 + q)*2;
            g_bmat[base]   = make_float4(M.m[0][0].re, M.m[0][0].im, M.m[0][1].re, M.m[0][1].im);
            g_bmat[base+1] = make_float4(M.m[1][0].re, M.m[1][0].im, M.m[1][1].re, M.m[1][1].im);
        }
        return;
    }
    t -= 256;
    if (t < 8) {                                     // final-layer VROT
        const float* wl = w + 2 * 48;
        C2 V = c2mul(mRZ(wl[26 + 3*t]), c2mul(mRY(wl[25 + 3*t]), mRX(wl[24 + 3*t])));
        g_vrot[t*2]   = make_float4(V.m[0][0].re, V.m[0][0].im, V.m[0][1].re, V.m[0][1].im);
        g_vrot[t*2+1] = make_float4(V.m[1][0].re, V.m[1][0].im, V.m[1][1].re, V.m[1][1].im);
        return;
    }
    t -= 8;
    if (t < 21) {                                    // entangler coeffs
        int layer = t / 7, p = t % 7;
        const float* wl = w + layer * 48 + 3 * p;
        float tx = wl[0], ty = wl[1], tz = wl[2];
        float sd, cd, ss, cs, sz, cz;
        sincosf(0.5f*(tx - ty), &sd, &cd);
        sincosf(0.5f*(tx + ty), &ss, &cs);
        sincosf(0.5f*tz,        &sz, &cz);
        float* o = g_xyz + t * 6;
        o[0]=cd; o[1]=sd; o[2]=cs; o[3]=ss; o[4]=cz; o[5]=sz;
        return;
    }
    t -= 21;
    if (t < 128) {                                   // init product factors
        int batch = t >> 3, q = t & 7;
        if (batch < nb) {
            float s, c; sincosf(0.5f * x[batch*8 + q], &s, &c);
            g_init[t] = make_float2(c - s, c + s);   // (amp|0>, amp|1>), 1/sqrt2 deferred
        }
        return;
    }
    t -= 128;
    if (t < out_n) out[t] = 0.f;                     // zero output
}

// ---------------- main kernel gate primitives ----------------

// Single-qubit gate on qubit Q (lane qubits 0-4, register qubits 5-7).
template<int Q>
__device__ __forceinline__ void apply1(float (&re)[8], float (&im)[8], unsigned lane,
                                       Cplx u00, Cplx u01, Cplx u10, Cplx u11) {
    if constexpr (Q < 5) {
        constexpr int m = 1 << Q;
        const bool hi = (lane & m) != 0;
        Cplx a = hi ? u11 : u00;
        Cplx b = hi ? u10 : u01;
#pragma unroll
        for (int r = 0; r < 8; r++) {
            float ore = __shfl_xor_sync(0xffffffffu, re[r], m);
            float oim = __shfl_xor_sync(0xffffffffu, im[r], m);
            float vre = re[r], vim = im[r];
            re[r] = a.re*vre - a.im*vim + b.re*ore - b.im*oim;
            im[r] = a.re*vim + a.im*vre + b.re*oim + b.im*ore;
        }
    } else {
        constexpr int rb = 1 << (Q - 5);
#pragma unroll
        for (int r = 0; r < 8; r++) {
            if (r & rb) continue;
            const int r1 = r | rb;
            float v0r = re[r],  v0i = im[r];
            float v1r = re[r1], v1i = im[r1];
            re[r]  = u00.re*v0r - u00.im*v0i + u01.re*v1r - u01.im*v1i;
            im[r]  = u00.re*v0i + u00.im*v0r + u01.re*v1i + u01.im*v1r;
            re[r1] = u10.re*v0r - u10.im*v0i + u11.re*v1r - u11.im*v1i;
            im[r1] = u10.re*v0i + u10.im*v0r + u11.re*v1i + u11.im*v1r;
        }
    }
}

// Fused RXX*RYY*RZZ on (Q1,Q2) using tabulated coeffs cf = {cd,sd,cs,ss,cz,sz}.
template<int Q1, int Q2>
__device__ __forceinline__ void xxyyzz(float (&re)[8], float (&im)[8], unsigned lane,
                                       const float* __restrict__ cf) {
    const float cd = cf[0], sd = cf[1], cs = cf[2], ss = cf[3], cz = cf[4], sz = cf[5];
    constexpr int lm = ((Q1 < 5) ? (1 << Q1) : 0) | ((Q2 < 5) ? (1 << Q2) : 0);
    constexpr int rm = ((Q1 >= 5) ? (1 << (Q1-5)) : 0) | ((Q2 >= 5) ? (1 << (Q2-5)) : 0);
    if constexpr (rm == 0) {
        const int p = (int)(((lane >> Q1) ^ (lane >> Q2)) & 1u);
        const float c = p ? cs : cd, s = p ? ss : sd, phim = p ? sz : -sz;
#pragma unroll
        for (int r = 0; r < 8; r++) {
            float wre = __shfl_xor_sync(0xffffffffu, re[r], lm);
            float wim = __shfl_xor_sync(0xffffffffu, im[r], lm);
            float tre = c*re[r] + s*wim;
            float tim = c*im[r] - s*wre;
            re[r] = cz*tre - phim*tim;
            im[r] = cz*tim + phim*tre;
        }
    } else {
#pragma unroll
        for (int r = 0; r < 8; r++) {
            const int pr = r ^ rm;
            if (r > pr) continue;
            float are = re[r],  aim = im[r];
            float bre = re[pr], bim = im[pr];
            float wa_re = bre, wa_im = bim, wb_re = are, wb_im = aim;
            if constexpr (lm != 0) {
                wa_re = __shfl_xor_sync(0xffffffffu, wa_re, lm);
                wa_im = __shfl_xor_sync(0xffffffffu, wa_im, lm);
                wb_re = __shfl_xor_sync(0xffffffffu, wb_re, lm);
                wb_im = __shfl_xor_sync(0xffffffffu, wb_im, lm);
            }
            const int da = (r << 5) | (int)lane;
            const int db = (pr << 5) | (int)lane;
            const int pa = ((da >> Q1) ^ (da >> Q2)) & 1;
            const int pb = ((db >> Q1) ^ (db >> Q2)) & 1;
            {
                float c = pa ? cs : cd, s = pa ? ss : sd, phim = pa ? sz : -sz;
                float tre = c*are + s*wa_im, tim = c*aim - s*wa_re;
                re[r] = cz*tre - phim*tim;  im[r] = cz*tim + phim*tre;
            }
            {
                float c = pb ? cs : cd, s = pb ? ss : sd, phim = pb ? sz : -sz;
                float tre = c*bre + s*wb_im, tim = c*bim - s*wb_re;
                re[pr] = cz*tre - phim*tim; im[pr] = cz*tim + phim*tre;
            }
        }
    }
}

// Controlled-RX(pi/4): control lane qubit QC, target lane qubit QT.
template<int QC, int QT>
__device__ __forceinline__ void crx8(float (&re)[8], float (&im)[8], unsigned lane) {
    const float c = 0.92387953251128674f;
    const float s = 0.38268343236508977f;
    constexpr int m = 1 << QT;
    const bool ctrl = ((lane >> QC) & 1) != 0;
#pragma unroll
    for (int r = 0; r < 8; r++) {
        float wre = __shfl_xor_sync(0xffffffffu, re[r], m);
        float wim = __shfl_xor_sync(0xffffffffu, im[r], m);
        if (ctrl) {
            float nr = c*re[r] + s*wim;
            float ni = c*im[r] - s*wre;
            re[r] = nr; im[r] = ni;
        }
    }
}

#define SQ(Q, MP) { const float4* mp_ = (MP);                                          \
    float4 m0_ = __ldg(mp_), m1_ = __ldg(mp_ + 1);                                     \
    apply1<Q>(re, im, lane, Cplx{m0_.x, m0_.y}, Cplx{m0_.z, m0_.w},                    \
              Cplx{m1_.x, m1_.y}, Cplx{m1_.z, m1_.w}); }

__global__ void __launch_bounds__(256)
qpie_main(float* __restrict__ out) {
    const unsigned lane = threadIdx.x & 31u;
    const int warpId    = threadIdx.x >> 5;
    const int batch     = blockIdx.x >> 3;
    const int path      = ((blockIdx.x & 7) << 3) | warpId;   // 0..63

    // ---- initial product state: (H then RY(x_q)) |0...0>, real amplitudes ----
    float re[8], im[8];
    {
        float2 iv[8];
#pragma unroll
        for (int q = 0; q < 8; q++) iv[q] = __ldg(&g_init[batch*8 + q]);
        float base = 1.f;
#pragma unroll
        for (int q = 0; q < 5; q++) base *= ((lane >> q) & 1u) ? iv[q].y : iv[q].x;
#pragma unroll
        for (int r = 0; r < 8; r++) {
            float p = base;
            p *= (r & 1) ? iv[5].y : iv[5].x;
            p *= (r & 2) ? iv[6].y : iv[6].x;
            p *= (r & 4) ? iv[7].y : iv[7].x;
            re[r] = p; im[r] = 0.f;
        }
    }

    for (int layer = 0; layer < 3; layer++) {
        const int combo = (path >> (2*layer)) & 3;
        const int r0 = combo & 1, r1 = (combo >> 1) & 1;

        // ---- ancilla block: per-branch diagonal factor (tabulated) ----
        {
            const float2* gb = g_branch + (layer*4 + combo)*256;
#pragma unroll
            for (int r = 0; r < 8; r++) {
                float2 g = __ldg(&gb[(r << 5) | lane]);
                float vr = re[r], vi = im[r];
                re[r] = g.x*vr - g.y*vi;
                im[r] = g.x*vi + g.y*vr;
            }
        }

        // ---- entanglers + CCRX (record control folded into branch value) ----
        const float* cf = g_xyz + layer*42;
        xxyyzz<0,1>(re, im, lane, cf + 0);
        if (r0) crx8<0,1>(re, im, lane);
        xxyyzz<2,3>(re, im, lane, cf + 6);
        if (r1) crx8<2,3>(re, im, lane);
        xxyyzz<4,5>(re, im, lane, cf + 12);
        xxyyzz<6,7>(re, im, lane, cf + 18);
        xxyyzz<1,2>(re, im, lane, cf + 24);
        xxyyzz<3,4>(re, im, lane, cf + 30);
        xxyyzz<5,6>(re, im, lane, cf + 36);

        // ---- single-qubit tail: fused [VROT * next-layer ROT(x)] or final VROT ----
        if (layer < 2) {
            const float4* bm = g_bmat + ((batch*2 + layer)*8)*2;
            SQ(0, bm + 0)  SQ(1, bm + 2)  SQ(2, bm + 4)  SQ(3, bm + 6)
            SQ(4, bm + 8)  SQ(5, bm + 10) SQ(6, bm + 12) SQ(7, bm + 14)
        } else {
            SQ(0, g_vrot + 0)  SQ(1, g_vrot + 2)  SQ(2, g_vrot + 4)  SQ(3, g_vrot + 6)
            SQ(4, g_vrot + 8)  SQ(5, g_vrot + 10) SQ(6, g_vrot + 12) SQ(7, g_vrot + 14)
        }
    }

    // ---- measurement: ev[q] = sum_d |amp|^2 * (1-2 d_q), scale 1/256 ----
    float ev[8];
#pragma unroll
    for (int q = 0; q < 8; q++) ev[q] = 0.f;
#pragma unroll
    for (int r = 0; r < 8; r++) {
        float p = re[r]*re[r] + im[r]*im[r];
        const int d = (r << 5) | (int)lane;
#pragma unroll
        for (int q = 0; q < 8; q++)
            ev[q] += ((d >> q) & 1) ? -p : p;
    }
#pragma unroll
    for (int off = 16; off >= 1; off >>= 1) {
#pragma unroll
        for (int q = 0; q < 8; q++)
            ev[q] += __shfl_xor_sync(0xffffffffu, ev[q], off);
    }

    __shared__ float sOut[8];
    if (threadIdx.x < 8) sOut[threadIdx.x] = 0.f;
    __syncthreads();
    if (lane < 8) atomicAdd(&sOut[lane], ev[lane]);
    __syncthreads();
    if (threadIdx.x < 8)
        atomicAdd(&out[batch*8 + threadIdx.x], sOut[threadIdx.x] * (1.f/256.f));
}

extern "C" void kernel_launch(void* const* d_in, const int* in_sizes, int n_in,
                              void* d_out, int out_size) {
    const float* x  = (const float*)d_in[0];   // [B, 8]
    const float* w  = (const float*)d_in[1];   // [3, 48]
    const float* pw = (const float*)d_in[2];   // [3, 2, 8]
    float* out = (float*)d_out;

    const int nb = in_sizes[0] / 8;            // 16
    qpie_precompute<<<15, 256>>>(x, w, pw, out, out_size, nb);
    qpie_main<<<nb * 8, 256>>>(out);
}

// round 5
// speedup vs baseline: 1.0936x; 1.0769x over previous
#include <cuda_runtime.h>

// ============================================================================
// QPIE simulator v4: each branch-path split across FOUR warps.
//   qubits 0-4 -> lane bits, qubit 5 -> 2 registers, qubits 6-7 -> warp id
//   within a 4-warp group. 4096 warps total (one resident wave, ~7/SMSP) to
//   hide SHFL latency; per-warp dependency chain is ~4x shorter than v3.
//   Cross-warp gates (3 per layer) via double-buffered smem + bar.sync(128).
// All batch/path-invariant trig is precomputed into device tables (as v3).
// ============================================================================

struct Cplx { float re, im; };
__device__ __forceinline__ Cplx cmul(Cplx a, Cplx b) {
    return { a.re*b.re - a.im*b.im, a.re*b.im + a.im*b.re };
}

// ---------------- device tables ----------------
__device__ float2 g_branch[3 * 4 * 256];     // [layer][r0+2*r1][d]
__device__ float4 g_bmat[16 * 2 * 8 * 2];    // [batch][bnd][q][row]
__device__ float4 g_vrot[8 * 2];             // final-layer VROT [q][row]
__device__ float  g_xyz[3 * 7 * 6];          // [layer][pair]: cd,sd,cs,ss,cz,sz
__device__ float2 g_init[16 * 8];            // [batch][q] init product factors

// ---------------- precompute ----------------
struct C2 { Cplx m[2][2]; };
__device__ __forceinline__ C2 c2mul(C2 A, C2 B) {
    C2 R;
    for (int i = 0; i < 2; i++)
        for (int j = 0; j < 2; j++) {
            Cplx s{0.f, 0.f};
            for (int k = 0; k < 2; k++) {
                Cplx p = cmul(A.m[i][k], B.m[k][j]);
                s.re += p.re; s.im += p.im;
            }
            R.m[i][j] = s;
        }
    return R;
}
__device__ __forceinline__ C2 mRX(float t) {
    float s, c; sincosf(0.5f*t, &s, &c);
    return C2{{{{c,0.f},{0.f,-s}},{{0.f,-s},{c,0.f}}}};
}
__device__ __forceinline__ C2 mRY(float t) {
    float s, c; sincosf(0.5f*t, &s, &c);
    return C2{{{{c,0.f},{-s,0.f}},{{s,0.f},{c,0.f}}}};
}
__device__ __forceinline__ C2 mRZ(float t) {
    float s, c; sincosf(0.5f*t, &s, &c);
    return C2{{{{c,-s},{0.f,0.f}},{{0.f,0.f},{c,s}}}};
}
__device__ __forceinline__ Cplx splitG(bool even, int rv, float s) {
    float sn, cn; sincosf(0.5f*s, &sn, &cn);
    if (even) {
        const float k = 0.70710678118654752f;
        return { k*cn, rv ? k*sn : -k*sn };
    }
    return rv ? Cplx{0.f, -sn} : Cplx{cn, 0.f};
}

__global__ void qpie_precompute(const float* __restrict__ x,
                                const float* __restrict__ w,
                                const float* __restrict__ pw,
                                float* __restrict__ out, int out_n, int nb) {
    int t = blockIdx.x * blockDim.x + threadIdx.x;

    if (t < 3072) {                                  // branch factor table
        int layer = t >> 10, rem = t & 1023;
        int combo = rem >> 8, d = rem & 255;
        int r0 = combo & 1, r1 = combo >> 1;
        bool even = (layer & 1) == 0;
        float s0 = 0.f, s1 = 0.f;
        for (int j = 0; j < 8; j++) {
            float b = (float)((d >> j) & 1);
            s0 += b * pw[layer*16 + j];
            s1 += b * pw[layer*16 + 8 + j];
        }
        Cplx g = cmul(splitG(even, r0, s0), splitG(even, r1, s1));
        g_branch[t] = make_float2(g.re, g.im);
        return;
    }
    t -= 3072;
    if (t < 256) {                                   // fused boundary matrices
        int batch = t >> 4, rem = t & 15;
        int bnd = rem >> 3, q = rem & 7;
        if (batch < nb) {
            const float* wl = w + bnd * 48;
            C2 V = c2mul(mRZ(wl[26 + 3*q]), c2mul(mRY(wl[25 + 3*q]), mRX(wl[24 + 3*q])));
            C2 R = (bnd == 0) ? mRX(x[batch*8 + q]) : mRY(x[batch*8 + q]);
            C2 M = c2mul(R, V);
            int base = ((batch*2 + bnd)*8 + q)*2;
            g_bmat[base]   = make_float4(M.m[0][0].re, M.m[0][0].im, M.m[0][1].re, M.m[0][1].im);
            g_bmat[base+1] = make_float4(M.m[1][0].re, M.m[1][0].im, M.m[1][1].re, M.m[1][1].im);
        }
        return;
    }
    t -= 256;
    if (t < 8) {                                     // final-layer VROT
        const float* wl = w + 2 * 48;
        C2 V = c2mul(mRZ(wl[26 + 3*t]), c2mul(mRY(wl[25 + 3*t]), mRX(wl[24 + 3*t])));
        g_vrot[t*2]   = make_float4(V.m[0][0].re, V.m[0][0].im, V.m[0][1].re, V.m[0][1].im);
        g_vrot[t*2+1] = make_float4(V.m[1][0].re, V.m[1][0].im, V.m[1][1].re, V.m[1][1].im);
        return;
    }
    t -= 8;
    if (t < 21) {                                    // entangler coeffs
        int layer = t / 7, p = t % 7;
        const float* wl = w + layer * 48 + 3 * p;
        float tx = wl[0], ty = wl[1], tz = wl[2];
        float sd, cd, ss, cs, sz, cz;
        sincosf(0.5f*(tx - ty), &sd, &cd);
        sincosf(0.5f*(tx + ty), &ss, &cs);
        sincosf(0.5f*tz,        &sz, &cz);
        float* o = g_xyz + t * 6;
        o[0]=cd; o[1]=sd; o[2]=cs; o[3]=ss; o[4]=cz; o[5]=sz;
        return;
    }
    t -= 21;
    if (t < 128) {                                   // init product factors
        int batch = t >> 3, q = t & 7;
        if (batch < nb) {
            float s, c; sincosf(0.5f * x[batch*8 + q], &s, &c);
            g_init[t] = make_float2(c - s, c + s);
        }
        return;
    }
    t -= 128;
    if (t < out_n) out[t] = 0.f;
}

// ---------------- main kernel primitives (2 register slots) ----------------

// Single-qubit gate on lane qubit Q<5.
template<int Q>
__device__ __forceinline__ void sq_lane(float (&vre)[2], float (&vim)[2], unsigned lane,
                                        Cplx u00, Cplx u01, Cplx u10, Cplx u11) {
    constexpr int m = 1 << Q;
    const bool hi = (lane & m) != 0;
    const Cplx a = hi ? u11 : u00;
    const Cplx b = hi ? u10 : u01;
#pragma unroll
    for (int r = 0; r < 2; r++) {
        float ore = __shfl_xor_sync(0xffffffffu, vre[r], m);
        float oim = __shfl_xor_sync(0xffffffffu, vim[r], m);
        float wre = vre[r], wim = vim[r];
        vre[r] = a.re*wre - a.im*wim + b.re*ore - b.im*oim;
        vim[r] = a.re*wim + a.im*wre + b.re*oim + b.im*ore;
    }
}

// Single-qubit gate on register qubit q5.
__device__ __forceinline__ void sq_reg(float (&vre)[2], float (&vim)[2],
                                       Cplx u00, Cplx u01, Cplx u10, Cplx u11) {
    float v0r = vre[0], v0i = vim[0], v1r = vre[1], v1i = vim[1];
    vre[0] = u00.re*v0r - u00.im*v0i + u01.re*v1r - u01.im*v1i;
    vim[0] = u00.re*v0i + u00.im*v0r + u01.re*v1i + u01.im*v1r;
    vre[1] = u10.re*v0r - u10.im*v0i + u11.re*v1r - u11.im*v1i;
    vim[1] = u10.re*v0i + u10.im*v0r + u11.re*v1i + u11.im*v1r;
}

// Fused RXX*RYY*RZZ kernel step given partner amplitude and parity.
__device__ __forceinline__ void ent_step(float& vr, float& vi, float wr, float wi, int p,
                                         float cd, float sd, float cs, float ss,
                                         float cz, float sz) {
    const float c = p ? cs : cd, s = p ? ss : sd, phim = p ? sz : -sz;
    float tre = c*vr + s*wi;
    float tim = c*vi - s*wr;
    vr = cz*tre - phim*tim;
    vi = cz*tim + phim*tre;
}

// Entangler on two lane qubits.
template<int Q1, int Q2>
__device__ __forceinline__ void ent_ll(float (&vre)[2], float (&vim)[2], unsigned lane,
                                       const float* __restrict__ cf) {
    const float cd = cf[0], sd = cf[1], cs = cf[2], ss = cf[3], cz = cf[4], sz = cf[5];
    constexpr int lm = (1 << Q1) | (1 << Q2);
    const int p = (int)(((lane >> Q1) ^ (lane >> Q2)) & 1u);
#pragma unroll
    for (int r = 0; r < 2; r++) {
        float wr = __shfl_xor_sync(0xffffffffu, vre[r], lm);
        float wi = __shfl_xor_sync(0xffffffffu, vim[r], lm);
        ent_step(vre[r], vim[r], wr, wi, p, cd, sd, cs, ss, cz, sz);
    }
}

// Entangler on (q4, q5): lane bit 4 + register bit.
__device__ __forceinline__ void ent_45(float (&vre)[2], float (&vim)[2], unsigned lane,
                                       const float* __restrict__ cf) {
    const float cd = cf[0], sd = cf[1], cs = cf[2], ss = cf[3], cz = cf[4], sz = cf[5];
    const int l4 = (int)((lane >> 4) & 1u);
    float w0r = __shfl_xor_sync(0xffffffffu, vre[1], 16);
    float w0i = __shfl_xor_sync(0xffffffffu, vim[1], 16);
    float w1r = __shfl_xor_sync(0xffffffffu, vre[0], 16);
    float w1i = __shfl_xor_sync(0xffffffffu, vim[0], 16);
    ent_step(vre[0], vim[0], w0r, w0i, l4 ^ 0, cd, sd, cs, ss, cz, sz);
    ent_step(vre[1], vim[1], w1r, w1i, l4 ^ 1, cd, sd, cs, ss, cz, sz);
}

// Controlled-RX(pi/4): control lane qubit QC, target lane qubit QT.
template<int QC, int QT>
__device__ __forceinline__ void crx_ll(float (&vre)[2], float (&vim)[2], unsigned lane) {
    const float c = 0.92387953251128674f;
    const float s = 0.38268343236508977f;
    constexpr int m = 1 << QT;
    const bool ctrl = ((lane >> QC) & 1u) != 0;
#pragma unroll
    for (int r = 0; r < 2; r++) {
        float wr = __shfl_xor_sync(0xffffffffu, vre[r], m);
        float wi = __shfl_xor_sync(0xffffffffu, vim[r], m);
        if (ctrl) {
            float nr = c*vre[r] + s*wi;
            float ni = c*vim[r] - s*wr;
            vre[r] = nr; vim[r] = ni;
        }
    }
}

#define GBAR(id) asm volatile("bar.sync %0, 128;" :: "r"(id) : "memory")

__global__ void __launch_bounds__(256)
qpie_main(float* __restrict__ out) {
    const int tid = threadIdx.x;
    const unsigned lane = tid & 31u;
    const int wib = tid >> 5;        // 0..7
    const int grp = wib >> 2;        // two independent path-groups per block
    const int W   = wib & 3;         // warp id in group: w0 = qubit6, w1 = qubit7
    const int w0  = W & 1, w1 = W >> 1;
    const int batch = blockIdx.x >> 5;
    const int path  = ((blockIdx.x & 31) << 1) | grp;  // 0..63
    const int barId = grp + 1;

    // exchange buffers: [grp][buf][W][reg][lane], double-buffered
    __shared__ float2 ex[2][2][4][2][32];
    __shared__ float sOut[8];
    if (tid < 8) sOut[tid] = 0.f;
    __syncthreads();

    // ---- initial product state (H then RY(x_q))|0>, real ----
    float vre[2], vim[2];
    {
        float2 iv[8];
#pragma unroll
        for (int q = 0; q < 8; q++) iv[q] = g_init[batch*8 + q];
        float base = 1.f;
#pragma unroll
        for (int q = 0; q < 5; q++) base *= ((lane >> q) & 1u) ? iv[q].y : iv[q].x;
        base *= w0 ? iv[6].y : iv[6].x;
        base *= w1 ? iv[7].y : iv[7].x;
        vre[0] = base * iv[5].x; vim[0] = 0.f;
        vre[1] = base * iv[5].y; vim[1] = 0.f;
    }

    int xc = 0;   // exchange counter -> buffer parity

    for (int layer = 0; layer < 3; layer++) {
        const int combo = (path >> (2*layer)) & 3;
        const int r0 = combo & 1, r1 = (combo >> 1) & 1;

        // ---- branch diagonal factor ----
        {
            const float2* gb = g_branch + (layer*4 + combo)*256 + (W << 6);
#pragma unroll
            for (int r = 0; r < 2; r++) {
                float2 g = __ldg(&gb[(r << 5) | lane]);
                float wr = vre[r], wi = vim[r];
                vre[r] = g.x*wr - g.y*wi;
                vim[r] = g.x*wi + g.y*wr;
            }
        }

        const float* cf = g_xyz + layer*42;

        // ---- entanglers (reference order) ----
        ent_ll<0,1>(vre, vim, lane, cf + 0);
        if (r0) crx_ll<0,1>(vre, vim, lane);
        ent_ll<2,3>(vre, vim, lane, cf + 6);
        if (r1) crx_ll<2,3>(vre, vim, lane);
        ent_45(vre, vim, lane, cf + 12);

        // (6,7): partner warp W^3, same reg/lane; parity = w0^w1
        {
            const float* c6 = cf + 18;
            int buf = xc & 1; xc++;
            ex[grp][buf][W][0][lane] = make_float2(vre[0], vim[0]);
            ex[grp][buf][W][1][lane] = make_float2(vre[1], vim[1]);
            GBAR(barId);
            float2 p0 = ex[grp][buf][W^3][0][lane];
            float2 p1 = ex[grp][buf][W^3][1][lane];
            const int p = w0 ^ w1;
            ent_step(vre[0], vim[0], p0.x, p0.y, p, c6[0], c6[1], c6[2], c6[3], c6[4], c6[5]);
            ent_step(vre[1], vim[1], p1.x, p1.y, p, c6[0], c6[1], c6[2], c6[3], c6[4], c6[5]);
        }

        ent_ll<1,2>(vre, vim, lane, cf + 24);
        ent_ll<3,4>(vre, vim, lane, cf + 30);

        // (5,6): partner warp W^1, opposite reg; parity = r ^ w0
        {
            const float* c5 = cf + 36;
            int buf = xc & 1; xc++;
            ex[grp][buf][W][0][lane] = make_float2(vre[0], vim[0]);
            ex[grp][buf][W][1][lane] = make_float2(vre[1], vim[1]);
            GBAR(barId);
            float2 p0 = ex[grp][buf][W^1][1][lane];   // my reg0 pairs with their reg1
            float2 p1 = ex[grp][buf][W^1][0][lane];
            ent_step(vre[0], vim[0], p0.x, p0.y, 0 ^ w0, c5[0], c5[1], c5[2], c5[3], c5[4], c5[5]);
            ent_step(vre[1], vim[1], p1.x, p1.y, 1 ^ w0, c5[0], c5[1], c5[2], c5[3], c5[4], c5[5]);
        }

        // ---- single-qubit tail: fused boundary matrices or final VROT ----
        const float4* M = (layer < 2) ? (g_bmat + (batch*2 + layer)*16) : g_vrot;
        {
            float4 a, b;
            a = __ldg(M+0);  b = __ldg(M+1);
            sq_lane<0>(vre, vim, lane, Cplx{a.x,a.y}, Cplx{a.z,a.w}, Cplx{b.x,b.y}, Cplx{b.z,b.w});
            a = __ldg(M+2);  b = __ldg(M+3);
            sq_lane<1>(vre, vim, lane, Cplx{a.x,a.y}, Cplx{a.z,a.w}, Cplx{b.x,b.y}, Cplx{b.z,b.w});
            a = __ldg(M+4);  b = __ldg(M+5);
            sq_lane<2>(vre, vim, lane, Cplx{a.x,a.y}, Cplx{a.z,a.w}, Cplx{b.x,b.y}, Cplx{b.z,b.w});
            a = __ldg(M+6);  b = __ldg(M+7);
            sq_lane<3>(vre, vim, lane, Cplx{a.x,a.y}, Cplx{a.z,a.w}, Cplx{b.x,b.y}, Cplx{b.z,b.w});
            a = __ldg(M+8);  b = __ldg(M+9);
            sq_lane<4>(vre, vim, lane, Cplx{a.x,a.y}, Cplx{a.z,a.w}, Cplx{b.x,b.y}, Cplx{b.z,b.w});
            a = __ldg(M+10); b = __ldg(M+11);
            sq_reg(vre, vim, Cplx{a.x,a.y}, Cplx{a.z,a.w}, Cplx{b.x,b.y}, Cplx{b.z,b.w});
        }
        // fused U6 (x) U7 on the two warp qubits: one exchange, 4x4 apply
        {
            float4 r6 = __ldg(M + 12 + w0);   // row w0 of U6
            float4 r7 = __ldg(M + 14 + w1);   // row w1 of U7
            Cplx u6[2] = { {r6.x, r6.y}, {r6.z, r6.w} };
            Cplx u7[2] = { {r7.x, r7.y}, {r7.z, r7.w} };
            Cplx cc[4];
#pragma unroll
            for (int Wp = 0; Wp < 4; Wp++) cc[Wp] = cmul(u7[Wp >> 1], u6[Wp & 1]);

            int buf = xc & 1; xc++;
            ex[grp][buf][W][0][lane] = make_float2(vre[0], vim[0]);
            ex[grp][buf][W][1][lane] = make_float2(vre[1], vim[1]);
            GBAR(barId);
#pragma unroll
            for (int r = 0; r < 2; r++) {
                float ar = 0.f, ai = 0.f;
#pragma unroll
                for (int Wp = 0; Wp < 4; Wp++) {
                    float2 v = ex[grp][buf][Wp][r][lane];
                    ar += cc[Wp].re*v.x - cc[Wp].im*v.y;
                    ai += cc[Wp].re*v.y + cc[Wp].im*v.x;
                }
                vre[r] = ar; vim[r] = ai;
            }
        }
    }

    // ---- measurement ----
    float ev[8];
#pragma unroll
    for (int q = 0; q < 8; q++) ev[q] = 0.f;
#pragma unroll
    for (int r = 0; r < 2; r++) {
        float p = vre[r]*vre[r] + vim[r]*vim[r];
        const int d = (r << 5) | (int)lane;
#pragma unroll
        for (int q = 0; q < 6; q++)
            ev[q] += ((d >> q) & 1) ? -p : p;
        ev[6] += w0 ? -p : p;
        ev[7] += w1 ? -p : p;
    }
#pragma unroll
    for (int off = 16; off >= 1; off >>= 1) {
#pragma unroll
        for (int q = 0; q < 8; q++)
            ev[q] += __shfl_xor_sync(0xffffffffu, ev[q], off);
    }
    if (lane < 8) atomicAdd(&sOut[lane], ev[lane]);
    __syncthreads();
    if (tid < 8)
        atomicAdd(&out[batch*8 + tid], sOut[tid] * (1.f/256.f));
}

extern "C" void kernel_launch(void* const* d_in, const int* in_sizes, int n_in,
                              void* d_out, int out_size) {
    const float* x  = (const float*)d_in[0];   // [B, 8]
    const float* w  = (const float*)d_in[1];   // [3, 48]
    const float* pw = (const float*)d_in[2];   // [3, 2, 8]
    float* out = (float*)d_out;

    const int nb = in_sizes[0] / 8;            // 16
    qpie_precompute<<<15, 256>>>(x, w, pw, out, out_size, nb);
    qpie_main<<<nb * 32, 256>>>(out);          // 512 blocks x 256 thr, one wave
}

// round 7
// speedup vs baseline: 1.3915x; 1.2723x over previous
#include <cuda_runtime.h>

// ============================================================================
// QPIE simulator v5: two-phase tree evaluation.
//  Phase A: 16 (c0,c1) prefixes per batch evolve layers 0-1 once, state -> L2.
//  Phase B: 64 paths per batch load prefix state, apply layer 2 + measure.
//  Eliminates the 2.3x redundant prefix recomputation of v4, the separate
//  precompute kernel (tables built per-block in smem), and wave imbalance.
//  Layout per 4-warp group: qubits 0-4 = lanes, 5 = 2 regs, 6-7 = warp id.
// ============================================================================

struct Cplx { float re, im; };
__device__ __forceinline__ Cplx cmul(Cplx a, Cplx b) {
    return { a.re*b.re - a.im*b.im, a.re*b.im + a.im*b.re };
}
struct C2 { Cplx m[2][2]; };
__device__ __forceinline__ C2 c2mul(C2 A, C2 B) {
    C2 R;
#pragma unroll
    for (int i = 0; i < 2; i++)
#pragma unroll
        for (int j = 0; j < 2; j++) {
            Cplx s{0.f, 0.f};
#pragma unroll
            for (int k = 0; k < 2; k++) {
                Cplx p = cmul(A.m[i][k], B.m[k][j]);
                s.re += p.re; s.im += p.im;
            }
            R.m[i][j] = s;
        }
    return R;
}
__device__ __forceinline__ C2 mRX(float t) {
    float s, c; sincosf(0.5f*t, &s, &c);
    return C2{{{{c,0.f},{0.f,-s}},{{0.f,-s},{c,0.f}}}};
}
__device__ __forceinline__ C2 mRY(float t) {
    float s, c; sincosf(0.5f*t, &s, &c);
    return C2{{{{c,0.f},{-s,0.f}},{{s,0.f},{c,0.f}}}};
}
__device__ __forceinline__ C2 mRZ(float t) {
    float s, c; sincosf(0.5f*t, &s, &c);
    return C2{{{{c,-s},{0.f,0.f}},{{0.f,0.f},{c,s}}}};
}

// prefix states: [group(<=512)][W][reg][lane] as float2
__device__ float2 g_state[512 * 256];

// ---- in-block table builders ----
__device__ __forceinline__ void make_tail(float4* dst, const float* wl, int q,
                                          int rotType, float xv) {
    C2 V = c2mul(mRZ(wl[26 + 3*q]), c2mul(mRY(wl[25 + 3*q]), mRX(wl[24 + 3*q])));
    if (rotType == 1)      V = c2mul(mRX(xv), V);
    else if (rotType == 2) V = c2mul(mRY(xv), V);
    dst[0] = make_float4(V.m[0][0].re, V.m[0][0].im, V.m[0][1].re, V.m[0][1].im);
    dst[1] = make_float4(V.m[1][0].re, V.m[1][0].im, V.m[1][1].re, V.m[1][1].im);
}
__device__ __forceinline__ void make_cf(float* o, const float* wl3) {
    float tx = wl3[0], ty = wl3[1], tz = wl3[2];
    float sd, cd, ss, cs, sz, cz;
    sincosf(0.5f*(tx - ty), &sd, &cd);
    sincosf(0.5f*(tx + ty), &ss, &cs);
    sincosf(0.5f*tz,        &sz, &cz);
    o[0]=cd; o[1]=sd; o[2]=cs; o[3]=ss; o[4]=cz; o[5]=sz;
}

// ---- gate primitives (2 register slots per thread) ----
template<int Q>
__device__ __forceinline__ void sq_lane(float (&vre)[2], float (&vim)[2], unsigned lane,
                                        Cplx u00, Cplx u01, Cplx u10, Cplx u11) {
    constexpr int m = 1 << Q;
    const bool hi = (lane & m) != 0;
    const Cplx a = hi ? u11 : u00;
    const Cplx b = hi ? u10 : u01;
#pragma unroll
    for (int r = 0; r < 2; r++) {
        float ore = __shfl_xor_sync(0xffffffffu, vre[r], m);
        float oim = __shfl_xor_sync(0xffffffffu, vim[r], m);
        float wre = vre[r], wim = vim[r];
        vre[r] = a.re*wre - a.im*wim + b.re*ore - b.im*oim;
        vim[r] = a.re*wim + a.im*wre + b.re*oim + b.im*ore;
    }
}
__device__ __forceinline__ void sq_reg(float (&vre)[2], float (&vim)[2],
                                       Cplx u00, Cplx u01, Cplx u10, Cplx u11) {
    float v0r = vre[0], v0i = vim[0], v1r = vre[1], v1i = vim[1];
    vre[0] = u00.re*v0r - u00.im*v0i + u01.re*v1r - u01.im*v1i;
    vim[0] = u00.re*v0i + u00.im*v0r + u01.re*v1i + u01.im*v1r;
    vre[1] = u10.re*v0r - u10.im*v0i + u11.re*v1r - u11.im*v1i;
    vim[1] = u10.re*v0i + u10.im*v0r + u11.re*v1i + u11.im*v1r;
}
__device__ __forceinline__ void ent_step(float& vr, float& vi, float wr, float wi, int p,
                                         float cd, float sd, float cs, float ss,
                                         float cz, float sz) {
    const float c = p ? cs : cd, s = p ? ss : sd, phim = p ? sz : -sz;
    float tre = c*vr + s*wi;
    float tim = c*vi - s*wr;
    vr = cz*tre - phim*tim;
    vi = cz*tim + phim*tre;
}
template<int Q1, int Q2>
__device__ __forceinline__ void ent_ll(float (&vre)[2], float (&vim)[2], unsigned lane,
                                       const float* __restrict__ cf) {
    const float cd = cf[0], sd = cf[1], cs = cf[2], ss = cf[3], cz = cf[4], sz = cf[5];
    constexpr int lm = (1 << Q1) | (1 << Q2);
    const int p = (int)(((lane >> Q1) ^ (lane >> Q2)) & 1u);
#pragma unroll
    for (int r = 0; r < 2; r++) {
        float wr = __shfl_xor_sync(0xffffffffu, vre[r], lm);
        float wi = __shfl_xor_sync(0xffffffffu, vim[r], lm);
        ent_step(vre[r], vim[r], wr, wi, p, cd, sd, cs, ss, cz, sz);
    }
}
__device__ __forceinline__ void ent_45(float (&vre)[2], float (&vim)[2], unsigned lane,
                                       const float* __restrict__ cf) {
    const float cd = cf[0], sd = cf[1], cs = cf[2], ss = cf[3], cz = cf[4], sz = cf[5];
    const int l4 = (int)((lane >> 4) & 1u);
    float w0r = __shfl_xor_sync(0xffffffffu, vre[1], 16);
    float w0i = __shfl_xor_sync(0xffffffffu, vim[1], 16);
    float w1r = __shfl_xor_sync(0xffffffffu, vre[0], 16);
    float w1i = __shfl_xor_sync(0xffffffffu, vim[0], 16);
    ent_step(vre[0], vim[0], w0r, w0i, l4 ^ 0, cd, sd, cs, ss, cz, sz);
    ent_step(vre[1], vim[1], w1r, w1i, l4 ^ 1, cd, sd, cs, ss, cz, sz);
}
template<int QC, int QT>
__device__ __forceinline__ void crx_ll(float (&vre)[2], float (&vim)[2], unsigned lane) {
    const float c = 0.92387953251128674f;
    const float s = 0.38268343236508977f;
    constexpr int m = 1 << QT;
    const bool ctrl = ((lane >> QC) & 1u) != 0;
#pragma unroll
    for (int r = 0; r < 2; r++) {
        float wr = __shfl_xor_sync(0xffffffffu, vre[r], m);
        float wi = __shfl_xor_sync(0xffffffffu, vim[r], m);
        if (ctrl) {
            float nr = c*vre[r] + s*wi;
            float ni = c*vim[r] - s*wr;
            vre[r] = nr; vim[r] = ni;
        }
    }
}

// on-the-fly ancilla branch factor (layer's pw slice in smem, 16 floats)
__device__ __forceinline__ void branch_mul(float (&vre)[2], float (&vim)[2],
                                           const float* __restrict__ sPW, unsigned lane,
                                           int w0, int w1, int r0, int r1, bool even) {
    float sl0 = 0.f, sl1 = 0.f;
#pragma unroll
    for (int j = 0; j < 5; j++) {
        float b = (float)((lane >> j) & 1u);
        sl0 += b * sPW[j];
        sl1 += b * sPW[8 + j];
    }
    if (w0) { sl0 += sPW[6];  sl1 += sPW[14]; }
    if (w1) { sl0 += sPW[7];  sl1 += sPW[15]; }
#pragma unroll
    for (int r = 0; r < 2; r++) {
        float s0 = sl0 + (r ? sPW[5]  : 0.f);
        float s1 = sl1 + (r ? sPW[13] : 0.f);
        float sn0, cn0, sn1, cn1;
        __sincosf(0.5f*s0, &sn0, &cn0);
        __sincosf(0.5f*s1, &sn1, &cn1);
        Cplx a, b;
        if (even) {
            const float k = 0.70710678118654752f;
            a = { k*cn0, r0 ? k*sn0 : -k*sn0 };
            b = { k*cn1, r1 ? k*sn1 : -k*sn1 };
        } else {
            a = r0 ? Cplx{0.f, -sn0} : Cplx{cn0, 0.f};
            b = r1 ? Cplx{0.f, -sn1} : Cplx{cn1, 0.f};
        }
        Cplx g = cmul(a, b);
        float wr = vre[r], wi = vim[r];
        vre[r] = g.re*wr - g.im*wi;
        vim[r] = g.re*wi + g.im*wr;
    }
}

template<bool NAMED>
__device__ __forceinline__ void grp_barrier(int id) {
    if constexpr (NAMED) asm volatile("bar.sync %0, 128;" :: "r"(id) : "memory");
    else __syncthreads();
}

// full entangler + single-qubit-tail section for one layer
template<bool NAMED>
__device__ __forceinline__ void layer_gates(float (&vre)[2], float (&vim)[2], unsigned lane,
                                            int W, int w0, int w1, int r0, int r1,
                                            const float* __restrict__ cf,
                                            const float4* __restrict__ M,
                                            float2* exg, int barId, int& xc) {
    ent_ll<0,1>(vre, vim, lane, cf + 0);
    if (r0) crx_ll<0,1>(vre, vim, lane);
    ent_ll<2,3>(vre, vim, lane, cf + 6);
    if (r1) crx_ll<2,3>(vre, vim, lane);
    ent_45(vre, vim, lane, cf + 12);

    // (6,7): partner warp W^3, parity w0^w1
    {
        const float* c6 = cf + 18;
        float2* b = exg + (xc & 1) * 256; xc++;
        b[W*64 + lane]      = make_float2(vre[0], vim[0]);
        b[W*64 + 32 + lane] = make_float2(vre[1], vim[1]);
        grp_barrier<NAMED>(barId);
        float2 p0 = b[(W^3)*64 + lane];
        float2 p1 = b[(W^3)*64 + 32 + lane];
        const int p = w0 ^ w1;
        ent_step(vre[0], vim[0], p0.x, p0.y, p, c6[0], c6[1], c6[2], c6[3], c6[4], c6[5]);
        ent_step(vre[1], vim[1], p1.x, p1.y, p, c6[0], c6[1], c6[2], c6[3], c6[4], c6[5]);
    }

    ent_ll<1,2>(vre, vim, lane, cf + 24);
    ent_ll<3,4>(vre, vim, lane, cf + 30);

    // (5,6): partner warp W^1, opposite reg, parity r^w0
    {
        const float* c5 = cf + 36;
        float2* b = exg + (xc & 1) * 256; xc++;
        b[W*64 + lane]      = make_float2(vre[0], vim[0]);
        b[W*64 + 32 + lane] = make_float2(vre[1], vim[1]);
        grp_barrier<NAMED>(barId);
        float2 p0 = b[(W^1)*64 + 32 + lane];
        float2 p1 = b[(W^1)*64 + lane];
        ent_step(vre[0], vim[0], p0.x, p0.y, 0 ^ w0, c5[0], c5[1], c5[2], c5[3], c5[4], c5[5]);
        ent_step(vre[1], vim[1], p1.x, p1.y, 1 ^ w0, c5[0], c5[1], c5[2], c5[3], c5[4], c5[5]);
    }

    // single-qubit tail: qubits 0-4 lanes, 5 reg
    {
        float4 a, b4;
        a = M[0];  b4 = M[1];
        sq_lane<0>(vre, vim, lane, Cplx{a.x,a.y}, Cplx{a.z,a.w}, Cplx{b4.x,b4.y}, Cplx{b4.z,b4.w});
        a = M[2];  b4 = M[3];
        sq_lane<1>(vre, vim, lane, Cplx{a.x,a.y}, Cplx{a.z,a.w}, Cplx{b4.x,b4.y}, Cplx{b4.z,b4.w});
        a = M[4];  b4 = M[5];
        sq_lane<2>(vre, vim, lane, Cplx{a.x,a.y}, Cplx{a.z,a.w}, Cplx{b4.x,b4.y}, Cplx{b4.z,b4.w});
        a = M[6];  b4 = M[7];
        sq_lane<3>(vre, vim, lane, Cplx{a.x,a.y}, Cplx{a.z,a.w}, Cplx{b4.x,b4.y}, Cplx{b4.z,b4.w});
        a = M[8];  b4 = M[9];
        sq_lane<4>(vre, vim, lane, Cplx{a.x,a.y}, Cplx{a.z,a.w}, Cplx{b4.x,b4.y}, Cplx{b4.z,b4.w});
        a = M[10]; b4 = M[11];
        sq_reg(vre, vim, Cplx{a.x,a.y}, Cplx{a.z,a.w}, Cplx{b4.x,b4.y}, Cplx{b4.z,b4.w});
    }
    // fused U6 (x) U7 on warp qubits: one exchange, 4x4 apply
    {
        float4 r6 = M[12 + w0];
        float4 r7 = M[14 + w1];
        Cplx u6[2] = { {r6.x, r6.y}, {r6.z, r6.w} };
        Cplx u7[2] = { {r7.x, r7.y}, {r7.z, r7.w} };
        Cplx cc[4];
#pragma unroll
        for (int Wp = 0; Wp < 4; Wp++) cc[Wp] = cmul(u7[Wp >> 1], u6[Wp & 1]);
        float2* b = exg + (xc & 1) * 256; xc++;
        b[W*64 + lane]      = make_float2(vre[0], vim[0]);
        b[W*64 + 32 + lane] = make_float2(vre[1], vim[1]);
        grp_barrier<NAMED>(barId);
#pragma unroll
        for (int r = 0; r < 2; r++) {
            float ar = 0.f, ai = 0.f;
#pragma unroll
            for (int Wp = 0; Wp < 4; Wp++) {
                float2 v = b[Wp*64 + r*32 + lane];
                ar += cc[Wp].re*v.x - cc[Wp].im*v.y;
                ai += cc[Wp].re*v.y + cc[Wp].im*v.x;
            }
            vre[r] = ar; vim[r] = ai;
        }
    }
}

// ---------------- Phase A: layers 0-1 for 16 prefixes/batch ----------------
__global__ void __launch_bounds__(256)
qpie_phaseA(const float* __restrict__ x, const float* __restrict__ w,
            const float* __restrict__ pw, float* __restrict__ out, int out_n) {
    const int tid = threadIdx.x;
    const unsigned lane = tid & 31u;
    const int wib = tid >> 5;
    const int grp = wib >> 2;
    const int W   = wib & 3;
    const int w0 = W & 1, w1 = W >> 1;
    const int batch = blockIdx.x >> 3;
    const int pf = ((blockIdx.x & 7) << 1) | grp;   // 0..15
    const int c0 = pf & 3, c1 = (pf >> 2) & 3;
    const int barId = grp + 1;

    __shared__ float4 sM[2][16];
    __shared__ float  sCF[2][42];
    __shared__ float2 sInit[8];
    __shared__ float  sPW[32];
    __shared__ float2 sEx[2][512];

    if (blockIdx.x == 0)
        for (int i = tid; i < out_n; i += 256) out[i] = 0.f;

    if (tid < 16) {
        int l = tid >> 3, q = tid & 7;
        make_tail(&sM[l][q*2], w + l*48, q, (l == 0) ? 1 : 2, x[batch*8 + q]);
    } else if (tid >= 32 && tid < 46) {
        int i = tid - 32, l = i / 7, p = i % 7;
        make_cf(&sCF[l][p*6], w + l*48 + 3*p);
    } else if (tid >= 64 && tid < 72) {
        int q = tid - 64;
        float s, c; sincosf(0.5f * x[batch*8 + q], &s, &c);
        sInit[q] = make_float2(c - s, c + s);
    } else if (tid >= 96 && tid < 128) {
        sPW[tid - 96] = pw[tid - 96];
    }
    __syncthreads();

    // initial product state (H then RY(x))|0>, 1/sqrt2^8 deferred
    float vre[2], vim[2];
    {
        float base = 1.f;
#pragma unroll
        for (int q = 0; q < 5; q++) base *= ((lane >> q) & 1u) ? sInit[q].y : sInit[q].x;
        base *= w0 ? sInit[6].y : sInit[6].x;
        base *= w1 ? sInit[7].y : sInit[7].x;
        vre[0] = base * sInit[5].x; vim[0] = 0.f;
        vre[1] = base * sInit[5].y; vim[1] = 0.f;
    }

    int xc = 0;
    // layer 0 (even)
    branch_mul(vre, vim, &sPW[0], lane, w0, w1, c0 & 1, (c0 >> 1) & 1, true);
    layer_gates<true>(vre, vim, lane, W, w0, w1, c0 & 1, (c0 >> 1) & 1,
                      sCF[0], sM[0], &sEx[grp][0], barId, xc);
    // layer 1 (odd)
    branch_mul(vre, vim, &sPW[16], lane, w0, w1, c1 & 1, (c1 >> 1) & 1, false);
    layer_gates<true>(vre, vim, lane, W, w0, w1, c1 & 1, (c1 >> 1) & 1,
                      sCF[1], sM[1], &sEx[grp][0], barId, xc);

    const int gidx = batch * 16 + pf;
    const int base = (gidx * 4 + W) * 64 + (int)lane;
    g_state[base]      = make_float2(vre[0], vim[0]);
    g_state[base + 32] = make_float2(vre[1], vim[1]);
}

// ---------------- Phase B: layer 2 + measurement, 64 paths/batch ----------------
__global__ void __launch_bounds__(128)
qpie_phaseB(const float* __restrict__ w, const float* __restrict__ pw,
            float* __restrict__ out) {
    const int tid = threadIdx.x;
    const unsigned lane = tid & 31u;
    const int W = tid >> 5;
    const int w0 = W & 1, w1 = W >> 1;
    const int batch = blockIdx.x >> 6;
    const int path  = blockIdx.x & 63;
    const int pf = path & 15, c2 = path >> 4;
    const int r0 = c2 & 1, r1 = (c2 >> 1) & 1;

    __shared__ float4 sM[16];
    __shared__ float  sCF[42];
    __shared__ float  sPW[16];
    __shared__ float2 sEx[512];
    __shared__ float  sOut[8];

    if (tid < 8) {
        make_tail(&sM[tid*2], w + 96, tid, 0, 0.f);
        sOut[tid] = 0.f;
    } else if (tid >= 16 && tid < 23) {
        int p = tid - 16;
        make_cf(&sCF[p*6], w + 96 + 3*p);
    } else if (tid >= 32 && tid < 48) {
        sPW[tid - 32] = pw[32 + (tid - 32)];
    }
    __syncthreads();

    // load prefix state
    float vre[2], vim[2];
    {
        const int base = ((batch*16 + pf) * 4 + W) * 64 + (int)lane;
        float2 v0 = g_state[base], v1 = g_state[base + 32];
        vre[0] = v0.x; vim[0] = v0.y;
        vre[1] = v1.x; vim[1] = v1.y;
    }
    // layer 2 (even)
    branch_mul(vre, vim, sPW, lane, w0, w1, r0, r1, true);
    int xc = 0;
    layer_gates<false>(vre, vim, lane, W, w0, w1, r0, r1, sCF, sM, sEx, 0, xc);

    // measurement
    float ev[8];
#pragma unroll
    for (int q = 0; q < 8; q++) ev[q] = 0.f;
#pragma unroll
    for (int r = 0; r < 2; r++) {
        float p = vre[r]*vre[r] + vim[r]*vim[r];
        const int d = (r << 5) | (int)lane;
#pragma unroll
        for (int q = 0; q < 6; q++)
            ev[q] += ((d >> q) & 1) ? -p : p;
        ev[6] += w0 ? -p : p;
        ev[7] += w1 ? -p : p;
    }
#pragma unroll
    for (int off = 16; off >= 1; off >>= 1) {
#pragma unroll
        for (int q = 0; q < 8; q++)
            ev[q] += __shfl_xor_sync(0xffffffffu, ev[q], off);
    }
    if (lane < 8) atomicAdd(&sOut[lane], ev[lane]);
    __syncthreads();
    if (tid < 8)
        atomicAdd(&out[batch*8 + tid], sOut[tid] * (1.f/256.f));
}

extern "C" void kernel_launch(void* const* d_in, const int* in_sizes, int n_in,
                              void* d_out, int out_size) {
    const float* x  = (const float*)d_in[0];   // [B, 8]
    const float* w  = (const float*)d_in[1];   // [3, 48]
    const float* pw = (const float*)d_in[2];   // [3, 2, 8]
    float* out = (float*)d_out;

    const int nb = in_sizes[0] / 8;            // 16
    qpie_phaseA<<<nb * 8,  256>>>(x, w, pw, out, out_size);
    qpie_phaseB<<<nb * 64, 128>>>(w, pw, out);
}

// round 8
// speedup vs baseline: 1.6391x; 1.1779x over previous
#include <cuda_runtime.h>

// ============================================================================
// QPIE simulator v6: two-phase tree evaluation.
//  Phase A: 16 (c0,c1) prefixes per batch evolve layers 0-1 once -> L2 state;
//           block 0 additionally builds phaseB's shared tables into globals.
//  Phase B: 64 paths per batch: copy tables (no trig), layer 2 + measurement
//           with a sign-tracking Walsh butterfly (20 SHFL instead of 40).
//  Layout per 4-warp group: qubits 0-4 = lanes, 5 = 2 regs, 6-7 = warp id.
// ============================================================================

struct Cplx { float re, im; };
__device__ __forceinline__ Cplx cmul(Cplx a, Cplx b) {
    return { a.re*b.re - a.im*b.im, a.re*b.im + a.im*b.re };
}
struct C2 { Cplx m[2][2]; };
__device__ __forceinline__ C2 c2mul(C2 A, C2 B) {
    C2 R;
#pragma unroll
    for (int i = 0; i < 2; i++)
#pragma unroll
        for (int j = 0; j < 2; j++) {
            Cplx s{0.f, 0.f};
#pragma unroll
            for (int k = 0; k < 2; k++) {
                Cplx p = cmul(A.m[i][k], B.m[k][j]);
                s.re += p.re; s.im += p.im;
            }
            R.m[i][j] = s;
        }
    return R;
}
__device__ __forceinline__ C2 mRX(float t) {
    float s, c; sincosf(0.5f*t, &s, &c);
    return C2{{{{c,0.f},{0.f,-s}},{{0.f,-s},{c,0.f}}}};
}
__device__ __forceinline__ C2 mRY(float t) {
    float s, c; sincosf(0.5f*t, &s, &c);
    return C2{{{{c,0.f},{-s,0.f}},{{s,0.f},{c,0.f}}}};
}
__device__ __forceinline__ C2 mRZ(float t) {
    float s, c; sincosf(0.5f*t, &s, &c);
    return C2{{{{c,-s},{0.f,0.f}},{{0.f,0.f},{c,s}}}};
}

// prefix states: [batch*16+prefix][W][reg][lane] as float2
__device__ float2 g_state[512 * 256];
// phaseB shared tables (built once by phaseA block 0)
__device__ float4 g_M2[16];     // layer-2 single-qubit tail matrices
__device__ float  g_CF2[42];    // layer-2 entangler coeffs
__device__ float  g_PW2[16];    // layer-2 phase weights

// ---- table builders ----
__device__ __forceinline__ void make_tail(float4* dst, const float* wl, int q,
                                          int rotType, float xv) {
    C2 V = c2mul(mRZ(wl[26 + 3*q]), c2mul(mRY(wl[25 + 3*q]), mRX(wl[24 + 3*q])));
    if (rotType == 1)      V = c2mul(mRX(xv), V);
    else if (rotType == 2) V = c2mul(mRY(xv), V);
    dst[0] = make_float4(V.m[0][0].re, V.m[0][0].im, V.m[0][1].re, V.m[0][1].im);
    dst[1] = make_float4(V.m[1][0].re, V.m[1][0].im, V.m[1][1].re, V.m[1][1].im);
}
__device__ __forceinline__ void make_cf(float* o, const float* wl3) {
    float tx = wl3[0], ty = wl3[1], tz = wl3[2];
    float sd, cd, ss, cs, sz, cz;
    sincosf(0.5f*(tx - ty), &sd, &cd);
    sincosf(0.5f*(tx + ty), &ss, &cs);
    sincosf(0.5f*tz,        &sz, &cz);
    o[0]=cd; o[1]=sd; o[2]=cs; o[3]=ss; o[4]=cz; o[5]=sz;
}

// ---- gate primitives (2 register slots per thread) ----
template<int Q>
__device__ __forceinline__ void sq_lane(float (&vre)[2], float (&vim)[2], unsigned lane,
                                        Cplx u00, Cplx u01, Cplx u10, Cplx u11) {
    constexpr int m = 1 << Q;
    const bool hi = (lane & m) != 0;
    const Cplx a = hi ? u11 : u00;
    const Cplx b = hi ? u10 : u01;
#pragma unroll
    for (int r = 0; r < 2; r++) {
        float ore = __shfl_xor_sync(0xffffffffu, vre[r], m);
        float oim = __shfl_xor_sync(0xffffffffu, vim[r], m);
        float wre = vre[r], wim = vim[r];
        vre[r] = a.re*wre - a.im*wim + b.re*ore - b.im*oim;
        vim[r] = a.re*wim + a.im*wre + b.re*oim + b.im*ore;
    }
}
__device__ __forceinline__ void sq_reg(float (&vre)[2], float (&vim)[2],
                                       Cplx u00, Cplx u01, Cplx u10, Cplx u11) {
    float v0r = vre[0], v0i = vim[0], v1r = vre[1], v1i = vim[1];
    vre[0] = u00.re*v0r - u00.im*v0i + u01.re*v1r - u01.im*v1i;
    vim[0] = u00.re*v0i + u00.im*v0r + u01.re*v1i + u01.im*v1r;
    vre[1] = u10.re*v0r - u10.im*v0i + u11.re*v1r - u11.im*v1i;
    vim[1] = u10.re*v0i + u10.im*v0r + u11.re*v1i + u11.im*v1r;
}
__device__ __forceinline__ void ent_step(float& vr, float& vi, float wr, float wi, int p,
                                         float cd, float sd, float cs, float ss,
                                         float cz, float sz) {
    const float c = p ? cs : cd, s = p ? ss : sd, phim = p ? sz : -sz;
    float tre = c*vr + s*wi;
    float tim = c*vi - s*wr;
    vr = cz*tre - phim*tim;
    vi = cz*tim + phim*tre;
}
template<int Q1, int Q2>
__device__ __forceinline__ void ent_ll(float (&vre)[2], float (&vim)[2], unsigned lane,
                                       const float* __restrict__ cf) {
    const float cd = cf[0], sd = cf[1], cs = cf[2], ss = cf[3], cz = cf[4], sz = cf[5];
    constexpr int lm = (1 << Q1) | (1 << Q2);
    const int p = (int)(((lane >> Q1) ^ (lane >> Q2)) & 1u);
#pragma unroll
    for (int r = 0; r < 2; r++) {
        float wr = __shfl_xor_sync(0xffffffffu, vre[r], lm);
        float wi = __shfl_xor_sync(0xffffffffu, vim[r], lm);
        ent_step(vre[r], vim[r], wr, wi, p, cd, sd, cs, ss, cz, sz);
    }
}
__device__ __forceinline__ void ent_45(float (&vre)[2], float (&vim)[2], unsigned lane,
                                       const float* __restrict__ cf) {
    const float cd = cf[0], sd = cf[1], cs = cf[2], ss = cf[3], cz = cf[4], sz = cf[5];
    const int l4 = (int)((lane >> 4) & 1u);
    float w0r = __shfl_xor_sync(0xffffffffu, vre[1], 16);
    float w0i = __shfl_xor_sync(0xffffffffu, vim[1], 16);
    float w1r = __shfl_xor_sync(0xffffffffu, vre[0], 16);
    float w1i = __shfl_xor_sync(0xffffffffu, vim[0], 16);
    ent_step(vre[0], vim[0], w0r, w0i, l4 ^ 0, cd, sd, cs, ss, cz, sz);
    ent_step(vre[1], vim[1], w1r, w1i, l4 ^ 1, cd, sd, cs, ss, cz, sz);
}
template<int QC, int QT>
__device__ __forceinline__ void crx_ll(float (&vre)[2], float (&vim)[2], unsigned lane) {
    const float c = 0.92387953251128674f;
    const float s = 0.38268343236508977f;
    constexpr int m = 1 << QT;
    const bool ctrl = ((lane >> QC) & 1u) != 0;
#pragma unroll
    for (int r = 0; r < 2; r++) {
        float wr = __shfl_xor_sync(0xffffffffu, vre[r], m);
        float wi = __shfl_xor_sync(0xffffffffu, vim[r], m);
        if (ctrl) {
            float nr = c*vre[r] + s*wi;
            float ni = c*vim[r] - s*wr;
            vre[r] = nr; vim[r] = ni;
        }
    }
}

// on-the-fly ancilla branch factor
__device__ __forceinline__ void branch_mul(float (&vre)[2], float (&vim)[2],
                                           const float* __restrict__ sPW, unsigned lane,
                                           int w0, int w1, int r0, int r1, bool even) {
    float sl0 = 0.f, sl1 = 0.f;
#pragma unroll
    for (int j = 0; j < 5; j++) {
        float b = (float)((lane >> j) & 1u);
        sl0 += b * sPW[j];
        sl1 += b * sPW[8 + j];
    }
    if (w0) { sl0 += sPW[6];  sl1 += sPW[14]; }
    if (w1) { sl0 += sPW[7];  sl1 += sPW[15]; }
#pragma unroll
    for (int r = 0; r < 2; r++) {
        float s0 = sl0 + (r ? sPW[5]  : 0.f);
        float s1 = sl1 + (r ? sPW[13] : 0.f);
        float sn0, cn0, sn1, cn1;
        __sincosf(0.5f*s0, &sn0, &cn0);
        __sincosf(0.5f*s1, &sn1, &cn1);
        Cplx a, b;
        if (even) {
            const float k = 0.70710678118654752f;
            a = { k*cn0, r0 ? k*sn0 : -k*sn0 };
            b = { k*cn1, r1 ? k*sn1 : -k*sn1 };
        } else {
            a = r0 ? Cplx{0.f, -sn0} : Cplx{cn0, 0.f};
            b = r1 ? Cplx{0.f, -sn1} : Cplx{cn1, 0.f};
        }
        Cplx g = cmul(a, b);
        float wr = vre[r], wi = vim[r];
        vre[r] = g.re*wr - g.im*wi;
        vim[r] = g.re*wi + g.im*wr;
    }
}

template<bool NAMED>
__device__ __forceinline__ void grp_barrier(int id) {
    if constexpr (NAMED) asm volatile("bar.sync %0, 128;" :: "r"(id) : "memory");
    else __syncthreads();
}

// full entangler + single-qubit-tail section for one layer
template<bool NAMED>
__device__ __forceinline__ void layer_gates(float (&vre)[2], float (&vim)[2], unsigned lane,
                                            int W, int w0, int w1, int r0, int r1,
                                            const float* __restrict__ cf,
                                            const float4* __restrict__ M,
                                            float2* exg, int barId, int& xc) {
    ent_ll<0,1>(vre, vim, lane, cf + 0);
    if (r0) crx_ll<0,1>(vre, vim, lane);
    ent_ll<2,3>(vre, vim, lane, cf + 6);
    if (r1) crx_ll<2,3>(vre, vim, lane);
    ent_45(vre, vim, lane, cf + 12);

    // (6,7): partner warp W^3, parity w0^w1
    {
        const float* c6 = cf + 18;
        float2* b = exg + (xc & 1) * 256; xc++;
        b[W*64 + lane]      = make_float2(vre[0], vim[0]);
        b[W*64 + 32 + lane] = make_float2(vre[1], vim[1]);
        grp_barrier<NAMED>(barId);
        float2 p0 = b[(W^3)*64 + lane];
        float2 p1 = b[(W^3)*64 + 32 + lane];
        const int p = w0 ^ w1;
        ent_step(vre[0], vim[0], p0.x, p0.y, p, c6[0], c6[1], c6[2], c6[3], c6[4], c6[5]);
        ent_step(vre[1], vim[1], p1.x, p1.y, p, c6[0], c6[1], c6[2], c6[3], c6[4], c6[5]);
    }

    ent_ll<1,2>(vre, vim, lane, cf + 24);
    ent_ll<3,4>(vre, vim, lane, cf + 30);

    // (5,6): partner warp W^1, opposite reg, parity r^w0
    {
        const float* c5 = cf + 36;
        float2* b = exg + (xc & 1) * 256; xc++;
        b[W*64 + lane]      = make_float2(vre[0], vim[0]);
        b[W*64 + 32 + lane] = make_float2(vre[1], vim[1]);
        grp_barrier<NAMED>(barId);
        float2 p0 = b[(W^1)*64 + 32 + lane];
        float2 p1 = b[(W^1)*64 + lane];
        ent_step(vre[0], vim[0], p0.x, p0.y, 0 ^ w0, c5[0], c5[1], c5[2], c5[3], c5[4], c5[5]);
        ent_step(vre[1], vim[1], p1.x, p1.y, 1 ^ w0, c5[0], c5[1], c5[2], c5[3], c5[4], c5[5]);
    }

    // single-qubit tail: qubits 0-4 lanes, 5 reg
    {
        float4 a, b4;
        a = M[0];  b4 = M[1];
        sq_lane<0>(vre, vim, lane, Cplx{a.x,a.y}, Cplx{a.z,a.w}, Cplx{b4.x,b4.y}, Cplx{b4.z,b4.w});
        a = M[2];  b4 = M[3];
        sq_lane<1>(vre, vim, lane, Cplx{a.x,a.y}, Cplx{a.z,a.w}, Cplx{b4.x,b4.y}, Cplx{b4.z,b4.w});
        a = M[4];  b4 = M[5];
        sq_lane<2>(vre, vim, lane, Cplx{a.x,a.y}, Cplx{a.z,a.w}, Cplx{b4.x,b4.y}, Cplx{b4.z,b4.w});
        a = M[6];  b4 = M[7];
        sq_lane<3>(vre, vim, lane, Cplx{a.x,a.y}, Cplx{a.z,a.w}, Cplx{b4.x,b4.y}, Cplx{b4.z,b4.w});
        a = M[8];  b4 = M[9];
        sq_lane<4>(vre, vim, lane, Cplx{a.x,a.y}, Cplx{a.z,a.w}, Cplx{b4.x,b4.y}, Cplx{b4.z,b4.w});
        a = M[10]; b4 = M[11];
        sq_reg(vre, vim, Cplx{a.x,a.y}, Cplx{a.z,a.w}, Cplx{b4.x,b4.y}, Cplx{b4.z,b4.w});
    }
    // fused U6 (x) U7 on warp qubits: one exchange, 4x4 apply
    {
        float4 r6 = M[12 + w0];
        float4 r7 = M[14 + w1];
        Cplx u6[2] = { {r6.x, r6.y}, {r6.z, r6.w} };
        Cplx u7[2] = { {r7.x, r7.y}, {r7.z, r7.w} };
        Cplx cc[4];
#pragma unroll
        for (int Wp = 0; Wp < 4; Wp++) cc[Wp] = cmul(u7[Wp >> 1], u6[Wp & 1]);
        float2* b = exg + (xc & 1) * 256; xc++;
        b[W*64 + lane]      = make_float2(vre[0], vim[0]);
        b[W*64 + 32 + lane] = make_float2(vre[1], vim[1]);
        grp_barrier<NAMED>(barId);
#pragma unroll
        for (int r = 0; r < 2; r++) {
            float ar = 0.f, ai = 0.f;
#pragma unroll
            for (int Wp = 0; Wp < 4; Wp++) {
                float2 v = b[Wp*64 + r*32 + lane];
                ar += cc[Wp].re*v.x - cc[Wp].im*v.y;
                ai += cc[Wp].re*v.y + cc[Wp].im*v.x;
            }
            vre[r] = ar; vim[r] = ai;
        }
    }
}

// ---------------- Phase A: layers 0-1 for 16 prefixes/batch ----------------
__global__ void __launch_bounds__(256)
qpie_phaseA(const float* __restrict__ x, const float* __restrict__ w,
            const float* __restrict__ pw, float* __restrict__ out, int out_n) {
    const int tid = threadIdx.x;
    const unsigned lane = tid & 31u;
    const int wib = tid >> 5;
    const int grp = wib >> 2;
    const int W   = wib & 3;
    const int w0 = W & 1, w1 = W >> 1;
    const int batch = blockIdx.x >> 3;
    const int pf = ((blockIdx.x & 7) << 1) | grp;   // 0..15
    const int c0 = pf & 3, c1 = (pf >> 2) & 3;
    const int barId = grp + 1;

    __shared__ float4 sM[2][16];
    __shared__ float  sCF[2][42];
    __shared__ float2 sInit[8];
    __shared__ float  sPW[32];
    __shared__ float2 sEx[2][512];

    if (blockIdx.x == 0) {
        // zero output + build phaseB's shared tables (once per grid)
        for (int i = tid; i < out_n; i += 256) out[i] = 0.f;
        if (tid >= 144 && tid < 152) {
            make_tail(&g_M2[(tid - 144)*2], w + 96, tid - 144, 0, 0.f);
        } else if (tid >= 160 && tid < 167) {
            make_cf(&g_CF2[(tid - 160)*6], w + 96 + 3*(tid - 160));
        } else if (tid >= 176 && tid < 192) {
            g_PW2[tid - 176] = pw[32 + (tid - 176)];
        }
    }

    if (tid < 16) {
        int l = tid >> 3, q = tid & 7;
        make_tail(&sM[l][q*2], w + l*48, q, (l == 0) ? 1 : 2, x[batch*8 + q]);
    } else if (tid >= 32 && tid < 46) {
        int i = tid - 32, l = i / 7, p = i % 7;
        make_cf(&sCF[l][p*6], w + l*48 + 3*p);
    } else if (tid >= 64 && tid < 72) {
        int q = tid - 64;
        float s, c; sincosf(0.5f * x[batch*8 + q], &s, &c);
        sInit[q] = make_float2(c - s, c + s);
    } else if (tid >= 96 && tid < 128) {
        sPW[tid - 96] = pw[tid - 96];
    }
    __syncthreads();

    // initial product state (H then RY(x))|0>, 1/sqrt2^8 deferred
    float vre[2], vim[2];
    {
        float base = 1.f;
#pragma unroll
        for (int q = 0; q < 5; q++) base *= ((lane >> q) & 1u) ? sInit[q].y : sInit[q].x;
        base *= w0 ? sInit[6].y : sInit[6].x;
        base *= w1 ? sInit[7].y : sInit[7].x;
        vre[0] = base * sInit[5].x; vim[0] = 0.f;
        vre[1] = base * sInit[5].y; vim[1] = 0.f;
    }

    int xc = 0;
    // layer 0 (even)
    branch_mul(vre, vim, &sPW[0], lane, w0, w1, c0 & 1, (c0 >> 1) & 1, true);
    layer_gates<true>(vre, vim, lane, W, w0, w1, c0 & 1, (c0 >> 1) & 1,
                      sCF[0], sM[0], &sEx[grp][0], barId, xc);
    // layer 1 (odd)
    branch_mul(vre, vim, &sPW[16], lane, w0, w1, c1 & 1, (c1 >> 1) & 1, false);
    layer_gates<true>(vre, vim, lane, W, w0, w1, c1 & 1, (c1 >> 1) & 1,
                      sCF[1], sM[1], &sEx[grp][0], barId, xc);

    const int gidx = batch * 16 + pf;
    const int base = (gidx * 4 + W) * 64 + (int)lane;
    g_state[base]      = make_float2(vre[0], vim[0]);
    g_state[base + 32] = make_float2(vre[1], vim[1]);
}

// ---------------- Phase B: layer 2 + measurement, 64 paths/batch ----------------
__global__ void __launch_bounds__(128)
qpie_phaseB(float* __restrict__ out) {
    const int tid = threadIdx.x;
    const unsigned lane = tid & 31u;
    const int W = tid >> 5;
    const int w0 = W & 1, w1 = W >> 1;
    const int batch = blockIdx.x >> 6;
    const int path  = blockIdx.x & 63;
    const int pf = path & 15, c2 = path >> 4;
    const int r0 = c2 & 1, r1 = (c2 >> 1) & 1;

    __shared__ float4 sM[16];
    __shared__ float  sCF[42];
    __shared__ float  sPW[16];
    __shared__ float2 sEx[512];
    __shared__ float  sOut[8];

    // flat copy of prebuilt tables (no trig, 1 load/thread)
    if (tid < 16)                 sPW[tid] = g_PW2[tid];
    else if (tid < 58)            sCF[tid - 16] = g_CF2[tid - 16];
    else if (tid >= 64 && tid < 80) sM[tid - 64] = g_M2[tid - 64];
    if (tid < 8) sOut[tid] = 0.f;
    __syncthreads();

    // load prefix state
    float vre[2], vim[2];
    {
        const int base = ((batch*16 + pf) * 4 + W) * 64 + (int)lane;
        float2 v0 = g_state[base], v1 = g_state[base + 32];
        vre[0] = v0.x; vim[0] = v0.y;
        vre[1] = v1.x; vim[1] = v1.y;
    }
    // layer 2 (even)
    branch_mul(vre, vim, sPW, lane, w0, w1, r0, r1, true);
    int xc = 0;
    layer_gates<false>(vre, vim, lane, W, w0, w1, r0, r1, sCF, sM, sEx, 0, xc);

    // ---- measurement: sign-tracking Walsh butterfly ----
    // A = p0+p1 reduced with per-bit signed sums extracted in-flight;
    // B = p0-p1 (q5) plain-reduced. ev6/ev7 = +/-A per warp.
    float p0 = vre[0]*vre[0] + vim[0]*vim[0];
    float p1 = vre[1]*vre[1] + vim[1]*vim[1];
    float A = p0 + p1, B = p0 - p1;
    float S[5];
#pragma unroll
    for (int k = 0; k < 5; k++) {
        const int mk = 1 << k;
        float Ap = __shfl_xor_sync(0xffffffffu, A, mk);
#pragma unroll
        for (int q = 0; q < 5; q++) {
            if (q < k) S[q] += __shfl_xor_sync(0xffffffffu, S[q], mk);
        }
        S[k] = ((lane >> k) & 1u) ? (Ap - A) : (A - Ap);
        A += Ap;
        B += __shfl_xor_sync(0xffffffffu, B, mk);
    }
    float v = S[0];
    if (lane == 1) v = S[1];
    else if (lane == 2) v = S[2];
    else if (lane == 3) v = S[3];
    else if (lane == 4) v = S[4];
    else if (lane == 5) v = B;
    else if (lane == 6) v = w0 ? -A : A;
    else if (lane == 7) v = w1 ? -A : A;
    if (lane < 8) atomicAdd(&sOut[lane], v);
    __syncthreads();
    if (tid < 8)
        atomicAdd(&out[batch*8 + tid], sOut[tid] * (1.f/256.f));
}

extern "C" void kernel_launch(void* const* d_in, const int* in_sizes, int n_in,
                              void* d_out, int out_size) {
    const float* x  = (const float*)d_in[0];   // [B, 8]
    const float* w  = (const float*)d_in[1];   // [3, 48]
    const float* pw = (const float*)d_in[2];   // [3, 2, 8]
    float* out = (float*)d_out;

    const int nb = in_sizes[0] / 8;            // 16
    qpie_phaseA<<<nb * 8,  256>>>(x, w, pw, out, out_size);
    qpie_phaseB<<<nb * 64, 128>>>(out);
}